// round 3
// baseline (speedup 1.0000x reference)
#include <cuda_runtime.h>

// Problem constants
#define BB      8
#define II      32
#define CC      8
#define OO      16
#define HHD     16          // pose dim h
#define MM      256         // OO*HHD
#define HW      256         // H*W
#define NROUTE  3

#define PPB     4           // pixels per block
#define THREADS 512
#define VROW    272         // swizzled row: 16 o-groups * 17
#define AROW    272

// Shared memory layout (float offsets)
static constexpr int SM_VOTES = 0;                            // [PPB*II][VROW] = 34816
static constexpr int SM_SX    = SM_VOTES + PPB * II * VROW;   // [PPB][II*CC]   = 1024
static constexpr int SM_LOG   = SM_SX    + PPB * II * CC;     // [PPB*II*OO]    = 2048
static constexpr int SM_ROUTE = SM_LOG   + PPB * II * OO;     // [PPB*II*OO]    = 2048
static constexpr int SM_ACT   = SM_ROUTE + PPB * II * OO;     // [PPB][AROW]    = 1088
static constexpr int SM_BIAS  = SM_ACT   + PPB * AROW;        // [MM]           = 256
static constexpr int SM_TOTAL = SM_BIAS  + MM;                // 41280 floats = 165120 B

__global__ __launch_bounds__(THREADS, 1)
void caps_routing_kernel(const float* __restrict__ x,
                         const float* __restrict__ w,
                         const float* __restrict__ bias,
                         float* __restrict__ out)
{
    extern __shared__ float sm[];
    float* s_votes = sm + SM_VOTES;
    float* s_sx    = sm + SM_SX;
    float* s_log   = sm + SM_LOG;
    float* s_route = sm + SM_ROUTE;
    float* s_act   = sm + SM_ACT;
    float* s_bias  = sm + SM_BIAS;

    const int t        = threadIdx.x;
    const int pixblock = blockIdx.x * PPB;     // global pixel index base (0..2047)
    const int b        = pixblock >> 8;        // PPB divides 256 -> same b for all 4
    const int pix0     = pixblock & 255;

    // ---- load bias, x-slice; zero logits ----
    if (t < MM) s_bias[t] = bias[t];

    #pragma unroll
    for (int k = t; k < PPB * II * CC; k += THREADS) {
        int p = k >> 8;
        int r = k & 255;
        int i = r >> 3;
        int c = r & 7;
        s_sx[k] = x[(((b * II + i) * CC + c) << 8) + pix0 + p];
    }
    #pragma unroll
    for (int k = t; k < PPB * II * OO; k += THREADS) s_log[k] = 0.0f;
    __syncthreads();

    // ---- votes[p][i][o*17+h] = sum_c x[p][i][c] * W[i][c][m] ----
    {
        const int m   = t & 255;
        const int o   = m >> 4;
        const int hh  = m & 15;
        const int col = o * 17 + hh;
        const int i0  = (t >> 8) * (II / 2);   // half the threads do i 0..15, half 16..31

        for (int i = i0; i < i0 + II / 2; ++i) {
            const float* wp  = w + (i * CC) * MM + m;
            const float* sx0 = s_sx + 0 * 256 + i * CC;
            const float* sx1 = s_sx + 1 * 256 + i * CC;
            const float* sx2 = s_sx + 2 * 256 + i * CC;
            const float* sx3 = s_sx + 3 * 256 + i * CC;
            float a0 = 0.f, a1 = 0.f, a2 = 0.f, a3 = 0.f;
            #pragma unroll
            for (int c = 0; c < CC; ++c) {
                float wv = wp[c * MM];     // coalesced across warp (m consecutive)
                a0 += sx0[c] * wv;
                a1 += sx1[c] * wv;
                a2 += sx2[c] * wv;
                a3 += sx3[c] * wv;
            }
            s_votes[(0 * II + i) * VROW + col] = a0;
            s_votes[(1 * II + i) * VROW + col] = a1;
            s_votes[(2 * II + i) * VROW + col] = a2;
            s_votes[(3 * II + i) * VROW + col] = a3;
        }
    }
    __syncthreads();

    // ---- routing iterations ----
    for (int r = 0; r < NROUTE; ++r) {
        // softmax over O per (p, i): 128 rows
        if (t < PPB * II) {
            const float* lg = s_log + t * OO;
            float*       rt = s_route + t * OO;
            float mx = lg[0];
            #pragma unroll
            for (int o = 1; o < OO; ++o) mx = fmaxf(mx, lg[o]);
            float e[OO];
            float sum = 0.f;
            #pragma unroll
            for (int o = 0; o < OO; ++o) { e[o] = __expf(lg[o] - mx); sum += e[o]; }
            float inv = 1.0f / sum;
            #pragma unroll
            for (int o = 0; o < OO; ++o) rt[o] = e[o] * inv;
        }
        __syncthreads();

        // preactivate + squash: 1024 (p, m) entries, 2 per thread
        #pragma unroll
        for (int k = 0; k < (PPB * MM) / THREADS; ++k) {
            int idx = t + k * THREADS;
            int p   = idx >> 8;
            int m   = idx & 255;
            int o   = m >> 4;
            int hh  = m & 15;
            const float* vp = s_votes + (p * II) * VROW + o * 17 + hh;
            const float* rp = s_route + (p * II) * OO + o;
            float acc = s_bias[m];
            #pragma unroll
            for (int i = 0; i < II; ++i) acc += rp[i * OO] * vp[i * VROW];

            // squash over h (16-lane groups, aligned inside the warp)
            float ns = acc * acc;
            ns += __shfl_xor_sync(0xffffffffu, ns, 1);
            ns += __shfl_xor_sync(0xffffffffu, ns, 2);
            ns += __shfl_xor_sync(0xffffffffu, ns, 4);
            ns += __shfl_xor_sync(0xffffffffu, ns, 8);
            float nrm   = sqrtf(ns);
            float scale = nrm / (1.0f + ns);     // s/||s|| * ||s||^2/(1+||s||^2)
            s_act[p * AROW + o * 17 + hh] = acc * scale;
        }
        __syncthreads();

        if (r < NROUTE - 1) {
            // distances: logits[p][i][o] += sum_h votes * act ; 2048 entries, 4/thread
            #pragma unroll
            for (int k = 0; k < (PPB * II * OO) / THREADS; ++k) {
                int idx = t + k * THREADS;
                int p   = idx >> 9;
                int rr  = idx & 511;
                int i   = rr >> 4;
                int o   = rr & 15;
                const float* vp = s_votes + (p * II + i) * VROW + o * 17;
                const float* ap = s_act + p * AROW + o * 17;
                float d = 0.f;
                #pragma unroll
                for (int hh = 0; hh < HHD; ++hh) d += vp[hh] * ap[hh];
                s_log[idx] += d;
            }
            __syncthreads();
        }
    }

    // ---- store activation: out[((b*256 + m))*256 + pix0 + p], p-fast for coalescing ----
    #pragma unroll
    for (int k = t; k < PPB * MM; k += THREADS) {
        int p  = k & 3;
        int m  = k >> 2;
        int o  = m >> 4;
        int hh = m & 15;
        out[((b * MM + m) << 8) + pix0 + p] = s_act[p * AROW + o * 17 + hh];
    }
}

extern "C" void kernel_launch(void* const* d_in, const int* in_sizes, int n_in,
                              void* d_out, int out_size)
{
    const float* x    = (const float*)d_in[0];   // (8,32,8,16,16)
    const float* w    = (const float*)d_in[1];   // (32,8,256)
    const float* bias = (const float*)d_in[2];   // (16,16,1,1)
    float* out = (float*)d_out;                  // (8,16,16,16,16)

    static bool attr_set = false;
    if (!attr_set) {
        cudaFuncSetAttribute(caps_routing_kernel,
                             cudaFuncAttributeMaxDynamicSharedMemorySize,
                             SM_TOTAL * (int)sizeof(float));
        attr_set = true;
    }

    const int n_pixels = BB * HW;                 // 2048
    dim3 grid(n_pixels / PPB);                    // 512
    dim3 block(THREADS);
    caps_routing_kernel<<<grid, block, SM_TOTAL * (int)sizeof(float)>>>(x, w, bias, out);
}

// round 7
// speedup vs baseline: 1.7604x; 1.7604x over previous
#include <cuda_runtime.h>

// Problem constants
#define BB      8
#define II      32
#define CC      8
#define OO      16
#define HHD     16          // pose dim h
#define MM      256         // OO*HHD
#define HW      256         // H*W
#define NROUTE  3

#define PPB     4           // pixels per block
#define THREADS 1024
#define VROW    272         // swizzled vote row: 16 o-groups * 17
#define AROW    272
#define RROW    36          // transposed route row stride (float4-aligned, bank-clean)

// Shared memory layout (float offsets)
static constexpr int SM_VOTES = 0;                            // [PPB*II][VROW] = 34816
static constexpr int SM_SX    = SM_VOTES + PPB * II * VROW;   // [PPB][II*CC]   = 1024
static constexpr int SM_LOG   = SM_SX    + PPB * II * CC;     // [PPB*II*OO]    = 2048
static constexpr int SM_ROUTE = SM_LOG   + PPB * II * OO;     // [PPB][OO*RROW] = 2304 (transposed: route[o][i])
static constexpr int SM_ACT   = SM_ROUTE + PPB * OO * RROW;   // [PPB][AROW]    = 1088
static constexpr int SM_BIAS  = SM_ACT   + PPB * AROW;        // [MM]           = 256
static constexpr int SM_TOTAL = SM_BIAS  + MM;                // 41536 floats = 166144 B

__global__ __launch_bounds__(THREADS, 1)
void caps_routing_kernel(const float* __restrict__ x,
                         const float* __restrict__ w,
                         const float* __restrict__ bias,
                         float* __restrict__ out)
{
    extern __shared__ float sm[];
    float* s_votes = sm + SM_VOTES;
    float* s_sx    = sm + SM_SX;
    float* s_log   = sm + SM_LOG;
    float* s_route = sm + SM_ROUTE;   // transposed: [p][o*RROW + i]
    float* s_act   = sm + SM_ACT;
    float* s_bias  = sm + SM_BIAS;

    const int t        = threadIdx.x;
    const int pixblock = blockIdx.x * PPB;     // global pixel index base (0..2047)
    const int b        = pixblock >> 8;        // PPB divides 256 -> same b for all 4
    const int pix0     = pixblock & 255;

    // ---- load bias, x-slice; zero logits ----
    if (t < MM) s_bias[t] = bias[t];

    {   // PPB*II*CC = 1024 entries, exactly 1 per thread
        int p = t >> 8;
        int r = t & 255;
        int i = r >> 3;
        int c = r & 7;
        s_sx[t] = x[(((b * II + i) * CC + c) << 8) + pix0 + p];
    }
    #pragma unroll
    for (int k = t; k < PPB * II * OO; k += THREADS) s_log[k] = 0.0f;
    __syncthreads();

    // ---- votes[p][i][o*17+h] = sum_c x[p][i][c] * W[i][c][m] ----
    {
        const int m   = t & 255;
        const int o   = m >> 4;
        const int hh  = m & 15;
        const int col = o * 17 + hh;
        const int i0  = (t >> 8) * (II / 4);   // 4 thread groups, 8 i's each

        #pragma unroll
        for (int i = i0; i < i0 + II / 4; ++i) {
            const float* wp  = w + (i * CC) * MM + m;
            const float* sx0 = s_sx + 0 * 256 + i * CC;
            const float* sx1 = s_sx + 1 * 256 + i * CC;
            const float* sx2 = s_sx + 2 * 256 + i * CC;
            const float* sx3 = s_sx + 3 * 256 + i * CC;
            float a0 = 0.f, a1 = 0.f, a2 = 0.f, a3 = 0.f;
            #pragma unroll
            for (int c = 0; c < CC; ++c) {
                float wv = wp[c * MM];     // coalesced across warp (m consecutive)
                a0 += sx0[c] * wv;
                a1 += sx1[c] * wv;
                a2 += sx2[c] * wv;
                a3 += sx3[c] * wv;
            }
            s_votes[(0 * II + i) * VROW + col] = a0;
            s_votes[(1 * II + i) * VROW + col] = a1;
            s_votes[(2 * II + i) * VROW + col] = a2;
            s_votes[(3 * II + i) * VROW + col] = a3;
        }
    }
    __syncthreads();

    // ---- routing iterations ----
    for (int r = 0; r < NROUTE; ++r) {
        // softmax over O per (p, i): 128 rows. Writes TRANSPOSED route[o][i].
        if (t < PPB * II) {
            const int p = t >> 5;
            const int i = t & 31;
            const float* lg = s_log + (p * II + i) * OO;
            float mx = lg[0];
            #pragma unroll
            for (int o = 1; o < OO; ++o) mx = fmaxf(mx, lg[o]);
            float e[OO];
            float sum = 0.f;
            #pragma unroll
            for (int o = 0; o < OO; ++o) { e[o] = __expf(lg[o] - mx); sum += e[o]; }
            float inv = 1.0f / sum;
            #pragma unroll
            for (int o = 0; o < OO; ++o)
                s_route[p * (OO * RROW) + o * RROW + i] = e[o] * inv;  // lanes: i consecutive -> bank-clean
        }
        __syncthreads();

        // preactivate + squash: 1024 (p, m) entries, 1 per thread
        {
            int p   = t >> 8;
            int m   = t & 255;
            int o   = m >> 4;
            int hh  = m & 15;
            const float*  vp  = s_votes + (p * II) * VROW + o * 17 + hh;
            const float4* rp4 = (const float4*)(s_route + p * (OO * RROW) + o * RROW);
            float acc = s_bias[m];
            #pragma unroll
            for (int j = 0; j < II / 4; ++j) {
                float4 r4 = rp4[j];                     // broadcast across 16 hh-lanes
                acc += r4.x * vp[(4 * j + 0) * VROW];
                acc += r4.y * vp[(4 * j + 1) * VROW];
                acc += r4.z * vp[(4 * j + 2) * VROW];
                acc += r4.w * vp[(4 * j + 3) * VROW];
            }

            // squash over h (16-lane groups, aligned inside the warp)
            float ns = acc * acc;
            ns += __shfl_xor_sync(0xffffffffu, ns, 1);
            ns += __shfl_xor_sync(0xffffffffu, ns, 2);
            ns += __shfl_xor_sync(0xffffffffu, ns, 4);
            ns += __shfl_xor_sync(0xffffffffu, ns, 8);
            float nrm   = sqrtf(ns);
            float scale = nrm / (1.0f + ns);     // s/||s|| * ||s||^2/(1+||s||^2)
            s_act[p * AROW + o * 17 + hh] = acc * scale;
        }
        __syncthreads();

        if (r < NROUTE - 1) {
            // distances: logits[p][i][o] += sum_h votes * act ; 2048 entries, 2/thread
            #pragma unroll
            for (int k = 0; k < (PPB * II * OO) / THREADS; ++k) {
                int idx = t + k * THREADS;
                int p   = idx >> 9;
                int rr  = idx & 511;
                int i   = rr >> 4;
                int o   = rr & 15;
                const float* vp = s_votes + (p * II + i) * VROW + o * 17;
                const float* ap = s_act + p * AROW + o * 17;
                float d = 0.f;
                #pragma unroll
                for (int hh = 0; hh < HHD; ++hh) d += vp[hh] * ap[hh];
                s_log[idx] += d;
            }
            __syncthreads();
        }
    }

    // ---- store activation: out[(b*256 + m)*256 + pix0 + p], p-fast for coalescing ----
    {
        int p  = t & 3;
        int m  = t >> 2;
        int o  = m >> 4;
        int hh = m & 15;
        out[((b * MM + m) << 8) + pix0 + p] = s_act[p * AROW + o * 17 + hh];
    }
}

extern "C" void kernel_launch(void* const* d_in, const int* in_sizes, int n_in,
                              void* d_out, int out_size)
{
    const float* x    = (const float*)d_in[0];   // (8,32,8,16,16)
    const float* w    = (const float*)d_in[1];   // (32,8,256)
    const float* bias = (const float*)d_in[2];   // (16,16,1,1)
    float* out = (float*)d_out;                  // (8,16,16,16,16)

    static bool attr_set = false;
    if (!attr_set) {
        cudaFuncSetAttribute(caps_routing_kernel,
                             cudaFuncAttributeMaxDynamicSharedMemorySize,
                             SM_TOTAL * (int)sizeof(float));
        attr_set = true;
    }

    const int n_pixels = BB * HW;                 // 2048
    dim3 grid(n_pixels / PPB);                    // 512
    dim3 block(THREADS);
    caps_routing_kernel<<<grid, block, SM_TOTAL * (int)sizeof(float)>>>(x, w, bias, out);
}

// round 9
// speedup vs baseline: 2.1990x; 1.2491x over previous
#include <cuda_runtime.h>

// Problem constants
#define BB      8
#define II      32
#define CC      8
#define OO      16
#define HHD     16          // pose dim h
#define MM      256         // OO*HHD
#define HW      256         // H*W
#define NROUTE  3

#define PPB     4           // pixels per block
#define THREADS 1024
#define LROW    17          // padded logit row (i stride), kills softmax bank conflicts
#define RROW    36          // transposed route row stride (float4-aligned, bank-clean)

// Shared memory layout (float offsets). Votes live in REGISTERS now.
static constexpr int SM_SX    = 0;                             // [PPB][II*CC]       = 1024
static constexpr int SM_LOG   = SM_SX    + PPB * II * CC;      // [PPB][II*LROW]     = 2176
static constexpr int SM_ROUTE = SM_LOG   + PPB * II * LROW;    // [PPB][OO*RROW]     = 2304
static constexpr int SM_PART  = SM_ROUTE + PPB * OO * RROW;    // [4g][PPB*MM]       = 4096
static constexpr int SM_ACT   = SM_PART  + 4 * PPB * MM / 4 * 4; // [PPB][MM]        = 1024
static constexpr int SM_BIAS  = SM_ACT   + PPB * MM;           // [MM]               = 256
static constexpr int SM_TOTAL = SM_BIAS  + MM;                 // 10880 floats = 43520 B

__global__ __launch_bounds__(THREADS, 1)
void caps_routing_kernel(const float* __restrict__ x,
                         const float* __restrict__ w,
                         const float* __restrict__ bias,
                         float* __restrict__ out)
{
    extern __shared__ float sm[];
    float* s_sx    = sm + SM_SX;
    float* s_log   = sm + SM_LOG;     // [p][i*17 + o]
    float* s_route = sm + SM_ROUTE;   // [p][o*36 + i]
    float* s_part  = sm + SM_PART;    // [g][p*256 + m]
    float* s_act   = sm + SM_ACT;     // [p][m]
    float* s_bias  = sm + SM_BIAS;

    const int t        = threadIdx.x;
    const int pixblock = blockIdx.x * PPB;
    const int b        = pixblock >> 8;        // PPB divides 256 -> same b for whole block
    const int pix0     = pixblock & 255;

    const int m  = t & 255;        // o*16 + hh
    const int g  = t >> 8;         // i-group: owns i in [g*8, g*8+8)
    const int o  = m >> 4;
    const int hh = m & 15;
    const int i0 = g * 8;

    // ---- init: bias, x-slice, zero logits ----
    if (t < MM) s_bias[t] = bias[t];
    {   // 1024 entries, 1/thread: s_sx[p][i*8+c]
        int p = t >> 8;
        int r = t & 255;
        int i = r >> 3;
        int c = r & 7;
        s_sx[t] = x[(((b * II + i) * CC + c) << 8) + pix0 + p];
    }
    for (int k = t; k < PPB * II * LROW; k += THREADS) s_log[k] = 0.0f;
    __syncthreads();

    // ---- votes in registers: v[p][il] = sum_c x[p][i0+il][c] * W[i0+il][c][m] ----
    float v[PPB][8];
    #pragma unroll
    for (int il = 0; il < 8; ++il) {
        const int i = i0 + il;
        const float* wp = w + (i * CC) * MM + m;
        float wreg[CC];
        #pragma unroll
        for (int c = 0; c < CC; ++c) wreg[c] = wp[c * MM];   // coalesced across m
        #pragma unroll
        for (int p = 0; p < PPB; ++p) {
            const float4* sx4 = (const float4*)(s_sx + p * 256 + i * 8);
            float4 s0 = sx4[0], s1 = sx4[1];                 // broadcast across lanes
            v[p][il] = s0.x * wreg[0] + s0.y * wreg[1] + s0.z * wreg[2] + s0.w * wreg[3]
                     + s1.x * wreg[4] + s1.y * wreg[5] + s1.z * wreg[6] + s1.w * wreg[7];
        }
    }
    __syncthreads();

    // ---- routing iterations ----
    for (int r = 0; r < NROUTE; ++r) {
        // softmax over O per (p, i): 128 rows. Writes TRANSPOSED route[p][o][i].
        if (t < PPB * II) {
            const int p = t >> 5;
            const int i = t & 31;
            const float* lg = s_log + p * (II * LROW) + i * LROW;
            float mx = lg[0];
            #pragma unroll
            for (int oo2 = 1; oo2 < OO; ++oo2) mx = fmaxf(mx, lg[oo2]);
            float e[OO];
            float sum = 0.f;
            #pragma unroll
            for (int oo2 = 0; oo2 < OO; ++oo2) { e[oo2] = __expf(lg[oo2] - mx); sum += e[oo2]; }
            float inv = 1.0f / sum;
            #pragma unroll
            for (int oo2 = 0; oo2 < OO; ++oo2)
                s_route[p * (OO * RROW) + oo2 * RROW + i] = e[oo2] * inv;   // i contiguous: bank-clean
        }
        __syncthreads();

        // preact partials: part[p] = sum_{il} route[p][o][i0+il] * v[p][il]
        #pragma unroll
        for (int p = 0; p < PPB; ++p) {
            const float4* rp = (const float4*)(s_route + p * (OO * RROW) + o * RROW + i0);
            float4 r0 = rp[0], r1 = rp[1];
            float part = r0.x * v[p][0] + r0.y * v[p][1] + r0.z * v[p][2] + r0.w * v[p][3]
                       + r1.x * v[p][4] + r1.y * v[p][5] + r1.z * v[p][6] + r1.w * v[p][7];
            s_part[g * (PPB * MM) + p * MM + m] = part;      // contiguous m: bank-clean
        }
        __syncthreads();

        // reduce 4 partials (thread role: pixel p = g), squash, write act
        {
            float acc = s_bias[m]
                      + s_part[0 * (PPB * MM) + g * MM + m]
                      + s_part[1 * (PPB * MM) + g * MM + m]
                      + s_part[2 * (PPB * MM) + g * MM + m]
                      + s_part[3 * (PPB * MM) + g * MM + m];
            // squash over h: 16-lane aligned groups
            float ns = acc * acc;
            ns += __shfl_xor_sync(0xffffffffu, ns, 1);
            ns += __shfl_xor_sync(0xffffffffu, ns, 2);
            ns += __shfl_xor_sync(0xffffffffu, ns, 4);
            ns += __shfl_xor_sync(0xffffffffu, ns, 8);
            float nrm   = sqrtf(ns);
            float scale = nrm / (1.0f + ns);                 // s/||s|| * ||s||^2/(1+||s||^2)
            s_act[g * MM + m] = acc * scale;                 // contiguous m: bank-clean
        }
        __syncthreads();

        if (r < NROUTE - 1) {
            // distances: logits[p][i][o] += sum_hh v[p][il]*act[p][m]
            // Register butterfly over the 16 hh lanes; 2 sets of 16 values (p-pairs).
            #pragma unroll
            for (int set = 0; set < 2; ++set) {
                const int p0 = set * 2;
                float a0 = s_act[(p0 + 0) * MM + m];
                float a1 = s_act[(p0 + 1) * MM + m];
                float dv[16];
                #pragma unroll
                for (int il = 0; il < 8; ++il) {
                    dv[il]     = v[p0 + 0][il] * a0;
                    dv[8 + il] = v[p0 + 1][il] * a1;
                }
                // stage mask=1: 16 -> 8
                {
                    int hb = hh & 1;
                    #pragma unroll
                    for (int j = 0; j < 8; ++j) {
                        float send = hb ? dv[j] : dv[j + 8];
                        float recv = __shfl_xor_sync(0xffffffffu, send, 1);
                        dv[j] = (hb ? dv[j + 8] : dv[j]) + recv;
                    }
                }
                // stage mask=2: 8 -> 4
                {
                    int hb = (hh >> 1) & 1;
                    #pragma unroll
                    for (int j = 0; j < 4; ++j) {
                        float send = hb ? dv[j] : dv[j + 4];
                        float recv = __shfl_xor_sync(0xffffffffu, send, 2);
                        dv[j] = (hb ? dv[j + 4] : dv[j]) + recv;
                    }
                }
                // stage mask=4: 4 -> 2
                {
                    int hb = (hh >> 2) & 1;
                    #pragma unroll
                    for (int j = 0; j < 2; ++j) {
                        float send = hb ? dv[j] : dv[j + 2];
                        float recv = __shfl_xor_sync(0xffffffffu, send, 4);
                        dv[j] = (hb ? dv[j + 2] : dv[j]) + recv;
                    }
                }
                // stage mask=8: 2 -> 1
                {
                    int hb = (hh >> 3) & 1;
                    float send = hb ? dv[0] : dv[1];
                    float recv = __shfl_xor_sync(0xffffffffu, send, 8);
                    dv[0] = (hb ? dv[1] : dv[0]) + recv;
                }
                // lane hh holds full h-sum for value jstar (bit-reversed hh)
                int jstar = ((hh & 1) << 3) | (((hh >> 1) & 1) << 2)
                          | (((hh >> 2) & 1) << 1) | ((hh >> 3) & 1);
                int p = p0 + (jstar >> 3);
                int i = i0 + (jstar & 7);
                s_log[p * (II * LROW) + i * LROW + o] += dv[0];
            }
            __syncthreads();
        }
    }

    // ---- store activation: out[(b*256 + m)*256 + pix0 + p]; float4 over 4 pixels ----
    if (t < MM) {
        float4 o4 = make_float4(s_act[0 * MM + t], s_act[1 * MM + t],
                                s_act[2 * MM + t], s_act[3 * MM + t]);
        *(float4*)(out + ((b * MM + t) << 8) + pix0) = o4;
    }
}

extern "C" void kernel_launch(void* const* d_in, const int* in_sizes, int n_in,
                              void* d_out, int out_size)
{
    const float* x    = (const float*)d_in[0];   // (8,32,8,16,16)
    const float* w    = (const float*)d_in[1];   // (32,8,256)
    const float* bias = (const float*)d_in[2];   // (16,16,1,1)
    float* out = (float*)d_out;                  // (8,16,16,16,16)

    const int n_pixels = BB * HW;                 // 2048
    dim3 grid(n_pixels / PPB);                    // 512
    dim3 block(THREADS);
    caps_routing_kernel<<<grid, block, SM_TOTAL * (int)sizeof(float)>>>(x, w, bias, out);
}

// round 10
// speedup vs baseline: 2.4668x; 1.1218x over previous
#include <cuda_runtime.h>

// Problem constants
#define BB      8
#define II      32
#define CC      8
#define OO      16
#define HHD     16          // pose dim h
#define MM      256         // OO*HHD
#define HW      256         // H*W
#define NROUTE  3

#define PPB     4           // pixels per block
#define THREADS 1024
#define LROW    17          // padded logit row (i stride), kills softmax bank conflicts
#define RROW    36          // transposed route row stride (float4-aligned, bank-clean)

// Shared memory layout (float offsets). Votes live in REGISTERS.
static constexpr int SM_SX    = 0;                             // [PPB][II*CC]       = 1024
static constexpr int SM_LOG   = SM_SX    + PPB * II * CC;      // [PPB][II*LROW]     = 2176
static constexpr int SM_ROUTE = SM_LOG   + PPB * II * LROW;    // [PPB][OO*RROW]     = 2304
static constexpr int SM_PART  = SM_ROUTE + PPB * OO * RROW;    // [4g][PPB*MM]       = 4096
static constexpr int SM_ACT   = SM_PART  + 4 * PPB * MM;       // [PPB][MM]          = 1024
static constexpr int SM_BIAS  = SM_ACT   + PPB * MM;           // [MM]               = 256
static constexpr int SM_TOTAL = SM_BIAS  + MM;                 // 10880 floats = 43520 B

__global__ __launch_bounds__(THREADS, 1)
void caps_routing_kernel(const float* __restrict__ x,
                         const float* __restrict__ w,
                         const float* __restrict__ bias,
                         float* __restrict__ out)
{
    extern __shared__ float sm[];
    float* s_sx    = sm + SM_SX;
    float* s_log   = sm + SM_LOG;     // [p][i*17 + o]
    float* s_route = sm + SM_ROUTE;   // [p][o*36 + i]
    float* s_part  = sm + SM_PART;    // [g][p*256 + m]
    float* s_act   = sm + SM_ACT;     // [p][m]
    float* s_bias  = sm + SM_BIAS;

    const int t        = threadIdx.x;
    const int pixblock = blockIdx.x * PPB;
    const int b        = pixblock >> 8;        // PPB divides 256 -> same b for whole block
    const int pix0     = pixblock & 255;

    const int m  = t & 255;        // o*16 + hh
    const int g  = t >> 8;         // i-group: owns i in [g*8, g*8+8)
    const int o  = m >> 4;
    const int hh = m & 15;
    const int i0 = g * 8;

    // ---- init: bias + vectorized x-slice (float4 over 4 pixels), zero logits ----
    if (t < MM) {
        s_bias[t] = bias[t];
        const int i = t >> 3;
        const int c = t & 7;
        const float4 xv = *(const float4*)(x + (((b * II + i) * CC + c) << 8) + pix0);
        s_sx[0 * 256 + t] = xv.x;          // s_sx[p][i*8+c]; bank-clean (stride-1 lanes)
        s_sx[1 * 256 + t] = xv.y;
        s_sx[2 * 256 + t] = xv.z;
        s_sx[3 * 256 + t] = xv.w;
    }
    for (int k = t; k < PPB * II * LROW; k += THREADS) s_log[k] = 0.0f;
    __syncthreads();

    // ---- votes in registers: v[p][il] = sum_c x[p][i0+il][c] * W[i0+il][c][m] ----
    float v[PPB][8];
    #pragma unroll
    for (int il = 0; il < 8; ++il) {
        const int i = i0 + il;
        const float* wp = w + (i * CC) * MM + m;
        float wreg[CC];
        #pragma unroll
        for (int c = 0; c < CC; ++c) wreg[c] = wp[c * MM];   // coalesced across m
        #pragma unroll
        for (int p = 0; p < PPB; ++p) {
            const float4* sx4 = (const float4*)(s_sx + p * 256 + i * 8);
            float4 s0 = sx4[0], s1 = sx4[1];                 // broadcast across lanes
            v[p][il] = s0.x * wreg[0] + s0.y * wreg[1] + s0.z * wreg[2] + s0.w * wreg[3]
                     + s1.x * wreg[4] + s1.y * wreg[5] + s1.z * wreg[6] + s1.w * wreg[7];
        }
    }
    __syncthreads();

    // ---- routing iterations ----
    for (int r = 0; r < NROUTE; ++r) {
        // softmax over O per (p, i): 128 rows x 8 threads each (ALL 1024 threads).
        // Thread (row, j) owns logits o=j and o=j+8; reduce over aligned 8-lane group.
        {
            const int row = t >> 3;           // (p,i) row
            const int j   = t & 7;
            const int p   = row >> 5;
            const int i   = row & 31;
            const float* lg = s_log + p * (II * LROW) + i * LROW;
            float l0 = lg[j];
            float l1 = lg[j + 8];
            float mx = fmaxf(l0, l1);
            mx = fmaxf(mx, __shfl_xor_sync(0xffffffffu, mx, 1));
            mx = fmaxf(mx, __shfl_xor_sync(0xffffffffu, mx, 2));
            mx = fmaxf(mx, __shfl_xor_sync(0xffffffffu, mx, 4));
            float e0 = __expf(l0 - mx);
            float e1 = __expf(l1 - mx);
            float s = e0 + e1;
            s += __shfl_xor_sync(0xffffffffu, s, 1);
            s += __shfl_xor_sync(0xffffffffu, s, 2);
            s += __shfl_xor_sync(0xffffffffu, s, 4);
            float inv = 1.0f / s;
            float* rt = s_route + p * (OO * RROW);
            rt[j * RROW + i]       = e0 * inv;   // bank = (4j + lane_row) % 32: all distinct
            rt[(j + 8) * RROW + i] = e1 * inv;
        }
        __syncthreads();

        // preact partials: part[p] = sum_{il} route[p][o][i0+il] * v[p][il]
        #pragma unroll
        for (int p = 0; p < PPB; ++p) {
            const float4* rp = (const float4*)(s_route + p * (OO * RROW) + o * RROW + i0);
            float4 r0 = rp[0], r1 = rp[1];
            float part = r0.x * v[p][0] + r0.y * v[p][1] + r0.z * v[p][2] + r0.w * v[p][3]
                       + r1.x * v[p][4] + r1.y * v[p][5] + r1.z * v[p][6] + r1.w * v[p][7];
            s_part[g * (PPB * MM) + p * MM + m] = part;      // contiguous m: bank-clean
        }
        __syncthreads();

        // reduce 4 partials (thread role: pixel p = g), squash, write act
        {
            float acc = s_bias[m]
                      + s_part[0 * (PPB * MM) + g * MM + m]
                      + s_part[1 * (PPB * MM) + g * MM + m]
                      + s_part[2 * (PPB * MM) + g * MM + m]
                      + s_part[3 * (PPB * MM) + g * MM + m];
            // squash over h: 16-lane aligned groups
            float ns = acc * acc;
            ns += __shfl_xor_sync(0xffffffffu, ns, 1);
            ns += __shfl_xor_sync(0xffffffffu, ns, 2);
            ns += __shfl_xor_sync(0xffffffffu, ns, 4);
            ns += __shfl_xor_sync(0xffffffffu, ns, 8);
            float nrm   = sqrtf(ns);
            float scale = nrm / (1.0f + ns);                 // s/||s|| * ||s||^2/(1+||s||^2)
            s_act[g * MM + m] = acc * scale;                 // contiguous m: bank-clean
        }
        __syncthreads();

        if (r < NROUTE - 1) {
            // distances: logits[p][i][o] += sum_hh v[p][il]*act[p][m]
            // Register butterfly over the 16 hh lanes; 2 sets of 16 values (p-pairs).
            #pragma unroll
            for (int set = 0; set < 2; ++set) {
                const int p0 = set * 2;
                float a0 = s_act[(p0 + 0) * MM + m];
                float a1 = s_act[(p0 + 1) * MM + m];
                float dv[16];
                #pragma unroll
                for (int il = 0; il < 8; ++il) {
                    dv[il]     = v[p0 + 0][il] * a0;
                    dv[8 + il] = v[p0 + 1][il] * a1;
                }
                // stage mask=1: 16 -> 8
                {
                    int hb = hh & 1;
                    #pragma unroll
                    for (int j = 0; j < 8; ++j) {
                        float send = hb ? dv[j] : dv[j + 8];
                        float recv = __shfl_xor_sync(0xffffffffu, send, 1);
                        dv[j] = (hb ? dv[j + 8] : dv[j]) + recv;
                    }
                }
                // stage mask=2: 8 -> 4
                {
                    int hb = (hh >> 1) & 1;
                    #pragma unroll
                    for (int j = 0; j < 4; ++j) {
                        float send = hb ? dv[j] : dv[j + 4];
                        float recv = __shfl_xor_sync(0xffffffffu, send, 2);
                        dv[j] = (hb ? dv[j + 4] : dv[j]) + recv;
                    }
                }
                // stage mask=4: 4 -> 2
                {
                    int hb = (hh >> 2) & 1;
                    #pragma unroll
                    for (int j = 0; j < 2; ++j) {
                        float send = hb ? dv[j] : dv[j + 2];
                        float recv = __shfl_xor_sync(0xffffffffu, send, 4);
                        dv[j] = (hb ? dv[j + 2] : dv[j]) + recv;
                    }
                }
                // stage mask=8: 2 -> 1
                {
                    int hb = (hh >> 3) & 1;
                    float send = hb ? dv[0] : dv[1];
                    float recv = __shfl_xor_sync(0xffffffffu, send, 8);
                    dv[0] = (hb ? dv[1] : dv[0]) + recv;
                }
                // lane hh holds full h-sum for value jstar (bit-reversed hh)
                int jstar = ((hh & 1) << 3) | (((hh >> 1) & 1) << 2)
                          | (((hh >> 2) & 1) << 1) | ((hh >> 3) & 1);
                int p = p0 + (jstar >> 3);
                int i = i0 + (jstar & 7);
                s_log[p * (II * LROW) + i * LROW + o] += dv[0];
            }
            __syncthreads();
        }
    }

    // ---- store activation: out[(b*256 + m)*256 + pix0 + p]; float4 over 4 pixels ----
    if (t < MM) {
        float4 o4 = make_float4(s_act[0 * MM + t], s_act[1 * MM + t],
                                s_act[2 * MM + t], s_act[3 * MM + t]);
        *(float4*)(out + ((b * MM + t) << 8) + pix0) = o4;
    }
}

extern "C" void kernel_launch(void* const* d_in, const int* in_sizes, int n_in,
                              void* d_out, int out_size)
{
    const float* x    = (const float*)d_in[0];   // (8,32,8,16,16)
    const float* w    = (const float*)d_in[1];   // (32,8,256)
    const float* bias = (const float*)d_in[2];   // (16,16,1,1)
    float* out = (float*)d_out;                  // (8,16,16,16,16)

    const int n_pixels = BB * HW;                 // 2048
    dim3 grid(n_pixels / PPB);                    // 512
    dim3 block(THREADS);
    caps_routing_kernel<<<grid, block, SM_TOTAL * (int)sizeof(float)>>>(x, w, bias, out);
}

// round 12
// speedup vs baseline: 2.5649x; 1.0398x over previous
#include <cuda_runtime.h>

// Problem constants
#define BB      8
#define II      32
#define CC      8
#define OO      16
#define HHD     16          // pose dim h
#define MM      256         // OO*HHD
#define HW      256         // H*W
#define NROUTE  3

#define PPB     2           // pixels per block (2 blocks co-resident per SM)
#define THREADS 512
#define LROW    17          // padded logit row (i stride)
#define RROW    36          // transposed route row stride (float4-aligned, bank-clean)

// Shared memory layout (float offsets). Votes live in REGISTERS.
static constexpr int SM_SX    = 0;                             // [PPB][II*CC]   = 512
static constexpr int SM_LOG   = SM_SX    + PPB * II * CC;      // [PPB][II*LROW] = 1088
static constexpr int SM_ROUTE = SM_LOG   + PPB * II * LROW;    // [PPB][OO*RROW] = 1152
static constexpr int SM_PART  = SM_ROUTE + PPB * OO * RROW;    // [2g][PPB*MM]   = 1024
static constexpr int SM_ACT   = SM_PART  + 2 * PPB * MM;       // [PPB][MM]      = 512
static constexpr int SM_BIAS  = SM_ACT   + PPB * MM;           // [MM]           = 256
static constexpr int SM_TOTAL = SM_BIAS  + MM;                 // 4544 floats = 18176 B

__global__ __launch_bounds__(THREADS, 2)
void caps_routing_kernel(const float* __restrict__ x,
                         const float* __restrict__ w,
                         const float* __restrict__ bias,
                         float* __restrict__ out)
{
    __shared__ float sm[SM_TOTAL];
    float* s_sx    = sm + SM_SX;      // [p][i*8+c]
    float* s_log   = sm + SM_LOG;     // [p][i*17 + o]
    float* s_route = sm + SM_ROUTE;   // [p][o*36 + i]
    float* s_part  = sm + SM_PART;    // [g][p*256 + m]
    float* s_act   = sm + SM_ACT;     // [p][m]
    float* s_bias  = sm + SM_BIAS;

    const int t        = threadIdx.x;
    const int pixblock = blockIdx.x * PPB;
    const int b        = pixblock >> 8;        // PPB divides 256 -> same b for whole block
    const int pix0     = pixblock & 255;       // even -> float2-aligned

    const int m  = t & 255;        // o*16 + hh
    const int g  = t >> 8;         // i-group: owns i in [g*16, g*16+16)
    const int o  = m >> 4;
    const int hh = m & 15;
    const int i0 = g * 16;

    // ---- init: bias + vectorized x-slice (float2 over 2 pixels), zero logits ----
    if (t < MM) {
        s_bias[t] = bias[t];
        const int i = t >> 3;
        const int c = t & 7;
        const float2 xv = *(const float2*)(x + (((b * II + i) * CC + c) << 8) + pix0);
        s_sx[0 * 256 + t] = xv.x;
        s_sx[1 * 256 + t] = xv.y;
    }
    for (int k = t; k < PPB * II * LROW; k += THREADS) s_log[k] = 0.0f;
    __syncthreads();

    // ---- votes in registers: v[p][il] = sum_c x[p][i0+il][c] * W[i0+il][c][m] ----
    float v[PPB][16];
    #pragma unroll
    for (int il = 0; il < 16; ++il) {
        const int i = i0 + il;
        const float* wp = w + (i * CC) * MM + m;
        float wreg[CC];
        #pragma unroll
        for (int c = 0; c < CC; ++c) wreg[c] = wp[c * MM];   // coalesced across m
        #pragma unroll
        for (int p = 0; p < PPB; ++p) {
            const float4* sx4 = (const float4*)(s_sx + p * 256 + i * 8);
            float4 s0 = sx4[0], s1 = sx4[1];                 // broadcast across lanes
            v[p][il] = s0.x * wreg[0] + s0.y * wreg[1] + s0.z * wreg[2] + s0.w * wreg[3]
                     + s1.x * wreg[4] + s1.y * wreg[5] + s1.z * wreg[6] + s1.w * wreg[7];
        }
    }
    __syncthreads();

    // ---- routing iterations ----
    for (int r = 0; r < NROUTE; ++r) {
        // softmax over O per (p, i): 64 rows x 8 threads each (ALL 512 threads).
        {
            const int row = t >> 3;           // (p,i) row: 0..63
            const int j   = t & 7;
            const int p   = row >> 5;
            const int i   = row & 31;
            const float* lg = s_log + p * (II * LROW) + i * LROW;
            float l0 = lg[j];
            float l1 = lg[j + 8];
            float mx = fmaxf(l0, l1);
            mx = fmaxf(mx, __shfl_xor_sync(0xffffffffu, mx, 1));
            mx = fmaxf(mx, __shfl_xor_sync(0xffffffffu, mx, 2));
            mx = fmaxf(mx, __shfl_xor_sync(0xffffffffu, mx, 4));
            float e0 = __expf(l0 - mx);
            float e1 = __expf(l1 - mx);
            float s = e0 + e1;
            s += __shfl_xor_sync(0xffffffffu, s, 1);
            s += __shfl_xor_sync(0xffffffffu, s, 2);
            s += __shfl_xor_sync(0xffffffffu, s, 4);
            float inv = 1.0f / s;
            float* rt = s_route + p * (OO * RROW);
            rt[j * RROW + i]       = e0 * inv;
            rt[(j + 8) * RROW + i] = e1 * inv;
        }
        __syncthreads();

        // preact partials: part[p] = sum_{il} route[p][o][i0+il] * v[p][il]
        #pragma unroll
        for (int p = 0; p < PPB; ++p) {
            const float4* rp = (const float4*)(s_route + p * (OO * RROW) + o * RROW + i0);
            float4 r0 = rp[0], r1 = rp[1], r2 = rp[2], r3 = rp[3];
            float part = r0.x * v[p][0]  + r0.y * v[p][1]  + r0.z * v[p][2]  + r0.w * v[p][3]
                       + r1.x * v[p][4]  + r1.y * v[p][5]  + r1.z * v[p][6]  + r1.w * v[p][7]
                       + r2.x * v[p][8]  + r2.y * v[p][9]  + r2.z * v[p][10] + r2.w * v[p][11]
                       + r3.x * v[p][12] + r3.y * v[p][13] + r3.z * v[p][14] + r3.w * v[p][15];
            s_part[g * (PPB * MM) + p * MM + m] = part;      // contiguous m: bank-clean
        }
        __syncthreads();

        // reduce 2 partials (thread role: pixel p = g), squash, write act
        {
            float acc = s_bias[m]
                      + s_part[0 * (PPB * MM) + g * MM + m]
                      + s_part[1 * (PPB * MM) + g * MM + m];
            // squash over h: 16-lane aligned groups
            float ns = acc * acc;
            ns += __shfl_xor_sync(0xffffffffu, ns, 1);
            ns += __shfl_xor_sync(0xffffffffu, ns, 2);
            ns += __shfl_xor_sync(0xffffffffu, ns, 4);
            ns += __shfl_xor_sync(0xffffffffu, ns, 8);
            float nrm   = sqrtf(ns);
            float scale = nrm / (1.0f + ns);                 // s/||s|| * ||s||^2/(1+||s||^2)
            s_act[g * MM + m] = acc * scale;                 // contiguous m: bank-clean
        }
        __syncthreads();

        if (r < NROUTE - 1) {
            // distances: logits[p][i][o] += sum_hh v[p][il]*act[p][m]
            // One pixel at a time (dv[16] live) to cap register pressure.
            #pragma unroll
            for (int p = 0; p < PPB; ++p) {
                float a = s_act[p * MM + m];
                float dv[16];
                #pragma unroll
                for (int il = 0; il < 16; ++il) dv[il] = v[p][il] * a;
                // butterfly over the 16 hh lanes: 16 values -> 1 per lane
                {   // mask=1: 16 -> 8 (lane bit0 <- value bit3)
                    int hb = hh & 1;
                    #pragma unroll
                    for (int j = 0; j < 8; ++j) {
                        float send = hb ? dv[j] : dv[j + 8];
                        float recv = __shfl_xor_sync(0xffffffffu, send, 1);
                        dv[j] = (hb ? dv[j + 8] : dv[j]) + recv;
                    }
                }
                {   // mask=2: 8 -> 4
                    int hb = (hh >> 1) & 1;
                    #pragma unroll
                    for (int j = 0; j < 4; ++j) {
                        float send = hb ? dv[j] : dv[j + 4];
                        float recv = __shfl_xor_sync(0xffffffffu, send, 2);
                        dv[j] = (hb ? dv[j + 4] : dv[j]) + recv;
                    }
                }
                {   // mask=4: 4 -> 2
                    int hb = (hh >> 2) & 1;
                    #pragma unroll
                    for (int j = 0; j < 2; ++j) {
                        float send = hb ? dv[j] : dv[j + 2];
                        float recv = __shfl_xor_sync(0xffffffffu, send, 4);
                        dv[j] = (hb ? dv[j + 2] : dv[j]) + recv;
                    }
                }
                {   // mask=8: 2 -> 1
                    int hb = (hh >> 3) & 1;
                    float send = hb ? dv[0] : dv[1];
                    float recv = __shfl_xor_sync(0xffffffffu, send, 8);
                    dv[0] = (hb ? dv[1] : dv[0]) + recv;
                }
                // lane hh holds the full h-sum for il = bitrev4(hh)
                int il = ((hh & 1) << 3) | (((hh >> 1) & 1) << 2)
                       | (((hh >> 2) & 1) << 1) | ((hh >> 3) & 1);
                int i = i0 + il;
                s_log[p * (II * LROW) + i * LROW + o] += dv[0];
            }
            __syncthreads();
        }
    }

    // ---- store activation: out[(b*256 + m)*256 + pix0 + p]; float2 over 2 pixels ----
    if (t < MM) {
        float2 o2 = make_float2(s_act[0 * MM + t], s_act[1 * MM + t]);
        *(float2*)(out + ((b * MM + t) << 8) + pix0) = o2;
    }
}

extern "C" void kernel_launch(void* const* d_in, const int* in_sizes, int n_in,
                              void* d_out, int out_size)
{
    const float* x    = (const float*)d_in[0];   // (8,32,8,16,16)
    const float* w    = (const float*)d_in[1];   // (32,8,256)
    const float* bias = (const float*)d_in[2];   // (16,16,1,1)
    float* out = (float*)d_out;                  // (8,16,16,16,16)

    const int n_pixels = BB * HW;                 // 2048
    dim3 grid(n_pixels / PPB);                    // 1024 blocks, 2 per SM
    dim3 block(THREADS);
    caps_routing_kernel<<<grid, block>>>(x, w, bias, out);
}